// round 2
// baseline (speedup 1.0000x reference)
#include <cuda_runtime.h>
#include <math.h>

#define GHH 224
#define GWW 224
#define PLANE (GHH*GWW)
#define TS 16
#define HALO 3
#define THALO (TS + 2*HALO)    // 22
#define NPIX (THALO*THALO)     // 484
#define CH 32
#define CHP 36                 // padded channel stride (bank-conflict-free float4)
#define NP 49

// Scratch (no allocations allowed): f0 after linear, plus ping-pong stage buffers.
__device__ float g_f0[8*972];
__device__ float g_bufA[8*3*PLANE];
__device__ float g_bufB[8*3*PLANE];

__device__ __forceinline__ int refl(int i, int n) {
    if (i < 0) i = -i;
    if (i >= n) i = 2*n - 2 - i;
    return i;
}

__device__ __forceinline__ float gelu_exact(float x) {
    return 0.5f * x * (1.0f + erff(x * 0.7071067811865476f));
}

// ---------------------------------------------------------------- linear ----
// g_f0[b,o] = x[b,:] . W[o,:] + bias[o]   (8 x 972, K=1000). One warp per output.
__global__ void linear_kernel(const float* __restrict__ x,
                              const float* __restrict__ w,
                              const float* __restrict__ bias)
{
    int gw = blockIdx.x * 4 + (threadIdx.x >> 5);
    int lane = threadIdx.x & 31;
    if (gw >= 8*972) return;
    int b = gw / 972, o = gw % 972;
    const float* xr = x + b*1000;
    const float* wr = w + o*1000;
    float s = 0.f;
    for (int k = lane; k < 1000; k += 32) s += xr[k] * wr[k];
    #pragma unroll
    for (int off = 16; off; off >>= 1) s += __shfl_xor_sync(0xffffffffu, s, off);
    if (lane == 0) g_f0[b*972 + o] = s + bias[o];
}

// ---------------------------------------------------------------- bicubic ----
__device__ __forceinline__ float cubicw(float d) {
    d = fabsf(d);
    const float a = -0.75f;
    if (d <= 1.f) return ((a + 2.f)*d - (a + 3.f))*d*d + 1.f;
    if (d <  2.f) return (((d - 5.f)*d + 8.f)*d - 4.f) * a;
    return 0.f;
}

// 18x18 -> 224x224, torch bicubic align_corners=False, border clamp (matches np.add.at clip)
__global__ void bicubic18_kernel()
{
    int idx = blockIdx.x * blockDim.x + threadIdx.x;
    if (idx >= 8*3*PLANE) return;
    int x  = idx % GWW;
    int y  = (idx / GWW) % GHH;
    int bc = idx / PLANE;           // b*3 + c
    float xs = (x + 0.5f) * (18.0f/224.0f) - 0.5f;
    float ys = (y + 0.5f) * (18.0f/224.0f) - 0.5f;
    int x0 = (int)floorf(xs), y0 = (int)floorf(ys);
    float tx = xs - (float)x0, ty = ys - (float)y0;
    float wx[4], wy[4]; int ix[4], iy[4];
    #pragma unroll
    for (int k = 0; k < 4; k++) {
        wx[k] = cubicw(tx - (float)(k-1)); ix[k] = min(max(x0 + k - 1, 0), 17);
        wy[k] = cubicw(ty - (float)(k-1)); iy[k] = min(max(y0 + k - 1, 0), 17);
    }
    const float* f = g_f0 + bc*324;
    float acc = 0.f;
    #pragma unroll
    for (int i = 0; i < 4; i++) {
        float r = 0.f;
        #pragma unroll
        for (int j = 0; j < 4; j++) r += wx[j] * f[iy[i]*18 + ix[j]];
        acc += wy[i] * r;
    }
    g_bufA[idx] = acc;
}

// ------------------------------------------------------------- fused JBU ----
// One block = one 16x16 output tile of one batch image for one stage.
// src_sel: 0 -> g_bufA, 1 -> g_bufB.  dst_sel: 0 -> g_bufA, 1 -> g_bufB, 2 -> ext.
__global__ __launch_bounds__(256, 2)
void jbu_kernel(const float* __restrict__ guidance,
                const float* __restrict__ w1, const float* __restrict__ b1,
                const float* __restrict__ w2, const float* __restrict__ b2,
                const float* __restrict__ temp_p, const float* __restrict__ sigma_p,
                int src_sel, int dst_sel, float* __restrict__ dst_ext)
{
    const float* hr_in = (src_sel == 0) ? g_bufA : g_bufB;
    float* out = (dst_sel == 2) ? dst_ext : ((dst_sel == 0) ? g_bufA : g_bufB);

    extern __shared__ float smem[];
    float* sq  = smem;                 // [NPIX][CHP]
    float* shr = sq  + NPIX*CHP;       // [3][NPIX]
    float* sw1 = shr + 3*NPIX;         // 96
    float* sb1 = sw1 + 96;             // 32
    float* sw2 = sb1 + 32;             // 1024
    float* sb2 = sw2 + 1024;           // 32
    float* ssp = sb2 + 32;             // 49

    const int tid = threadIdx.x;
    const int b   = blockIdx.z;
    const int ty0 = blockIdx.y * TS, tx0 = blockIdx.x * TS;

    for (int i = tid; i < 96;   i += 256) sw1[i] = w1[i];
    for (int i = tid; i < 1024; i += 256) sw2[i] = w2[i];
    if (tid < 32) { sb1[tid] = b1[tid]; sb2[tid] = b2[tid]; }
    if (tid < NP) {
        float sig = *sigma_p;
        int di = tid / 7, dj = tid % 7;
        float dy = -1.0f + (float)di * (1.0f/3.0f);
        float dx = -1.0f + (float)dj * (1.0f/3.0f);
        ssp[tid] = expf(-(dy*dy + dx*dx) / (2.0f*sig*sig));
    }
    __syncthreads();

    const float* gb = guidance + (size_t)b * 3 * PLANE;
    const float* hb = hr_in    + (size_t)b * 3 * PLANE;

    // Fill halo tile: hr channels + q (range_proj of guidance), reflect-padded.
    for (int i = tid; i < NPIX; i += 256) {
        int ly = i / THALO, lx = i % THALO;
        int gy = refl(ty0 + ly - HALO, GHH);
        int gx = refl(tx0 + lx - HALO, GWW);
        int gi = gy * GWW + gx;
        float g0 = gb[gi], g1 = gb[PLANE + gi], g2 = gb[2*PLANE + gi];
        shr[i]        = hb[gi];
        shr[NPIX+i]   = hb[PLANE + gi];
        shr[2*NPIX+i] = hb[2*PLANE + gi];
        float h[CH];
        #pragma unroll
        for (int k = 0; k < CH; k++) {
            float v = sw1[k*3]*g0 + sw1[k*3+1]*g1 + sw1[k*3+2]*g2 + sb1[k];
            h[k] = gelu_exact(v);
        }
        float* qd = sq + i * CHP;
        #pragma unroll
        for (int j = 0; j < CH; j++) {
            float v = sb2[j];
            const float4* wr = (const float4*)(sw2 + j*CH);
            #pragma unroll
            for (int k4 = 0; k4 < 8; k4++) {
                float4 ww = wr[k4];
                v += ww.x*h[4*k4] + ww.y*h[4*k4+1] + ww.z*h[4*k4+2] + ww.w*h[4*k4+3];
            }
            qd[j] = v;
        }
    }
    __syncthreads();

    const int ty = tid / TS, tx = tid % TS;
    const int base = ty * THALO + tx;                  // top-left (di=0,dj=0) tap
    const float* qb = sq + base * CHP;
    const float* qc = sq + (base + HALO*THALO + HALO) * CHP;

    float s[NP];
    #pragma unroll
    for (int p = 0; p < NP; p++) s[p] = 0.f;

    #pragma unroll 1
    for (int c4 = 0; c4 < 8; c4++) {
        float4 ctr = *(const float4*)(qc + 4*c4);
        #pragma unroll
        for (int p = 0; p < NP; p++) {
            const int di = p / 7, dj = p % 7;
            float4 t = *(const float4*)(qb + (di*THALO + dj)*CHP + 4*c4);
            s[p] += ctr.x*t.x + ctr.y*t.y + ctr.z*t.z + ctr.w*t.w;
        }
    }

    float tmp = expf(*temp_p);
    tmp = fminf(fmaxf(tmp, 1e-4f), 1e4f);

    float m = -1e30f;
    #pragma unroll
    for (int p = 0; p < NP; p++) { s[p] *= tmp; m = fmaxf(m, s[p]); }
    float sum = 0.f;
    #pragma unroll
    for (int p = 0; p < NP; p++) {
        float e = __expf(s[p] - m) * ssp[p];
        s[p] = e; sum += e;
    }
    float inv = 1.0f / fmaxf(sum, 1e-7f);

    float o0 = 0.f, o1 = 0.f, o2 = 0.f;
    #pragma unroll
    for (int p = 0; p < NP; p++) {
        const int di = p / 7, dj = p % 7;
        int ti = base + di*THALO + dj;
        o0 += s[p] * shr[ti];
        o1 += s[p] * shr[NPIX + ti];
        o2 += s[p] * shr[2*NPIX + ti];
    }
    int y = ty0 + ty, x = tx0 + tx;
    size_t ob = (size_t)b * 3 * PLANE + (size_t)y * GWW + x;
    out[ob]           = o0 * inv;
    out[ob +   PLANE] = o1 * inv;
    out[ob + 2*PLANE] = o2 * inv;
}

// ----------------------------------------------------------------- launch ----
extern "C" void kernel_launch(void* const* d_in, const int* in_sizes, int n_in,
                              void* d_out, int out_size)
{
    const float* x      = (const float*)d_in[0];
    const float* gd     = (const float*)d_in[1];
    const float* lw     = (const float*)d_in[2];
    const float* lb     = (const float*)d_in[3];
    const float* w1s    = (const float*)d_in[4];
    const float* b1s    = (const float*)d_in[5];
    const float* w2s    = (const float*)d_in[6];
    const float* b2s    = (const float*)d_in[7];
    const float* temps  = (const float*)d_in[8];
    const float* sigmas = (const float*)d_in[9];
    float* out = (float*)d_out;

    const int smem = (NPIX*CHP + 3*NPIX + 96 + 32 + 1024 + 32 + 49) * (int)sizeof(float);
    static int smem_set = 0;
    if (!smem_set) {
        cudaFuncSetAttribute(jbu_kernel, cudaFuncAttributeMaxDynamicSharedMemorySize, smem);
        smem_set = 1;
    }

    linear_kernel<<<(8*972 + 3)/4, 128>>>(x, lw, lb);

    // bicubic 18->224 into bufA (only stage 1 needs a real resize; 224->224 is identity)
    bicubic18_kernel<<<(8*3*PLANE + 255)/256, 256>>>();

    dim3 grid(GWW/TS, GHH/TS, 8);
    // stage 1: A -> B
    jbu_kernel<<<grid, 256, smem>>>(gd, w1s + 0*96, b1s + 0*32, w2s + 0*1024, b2s + 0*32,
                                    temps + 0, sigmas + 0, /*src*/0, /*dst*/1, nullptr);
    // stage 2: B -> A
    jbu_kernel<<<grid, 256, smem>>>(gd, w1s + 1*96, b1s + 1*32, w2s + 1*1024, b2s + 1*32,
                                    temps + 1, sigmas + 1, 1, 0, nullptr);
    // stage 3: A -> B
    jbu_kernel<<<grid, 256, smem>>>(gd, w1s + 2*96, b1s + 2*32, w2s + 2*1024, b2s + 2*32,
                                    temps + 2, sigmas + 2, 0, 1, nullptr);
    // stage 4: B -> d_out
    jbu_kernel<<<grid, 256, smem>>>(gd, w1s + 3*96, b1s + 3*32, w2s + 3*1024, b2s + 3*32,
                                    temps + 3, sigmas + 3, 1, 2, out);
}

// round 4
// speedup vs baseline: 1.2948x; 1.2948x over previous
#include <cuda_runtime.h>
#include <cuda_fp16.h>
#include <math.h>

#define GHH 224
#define GWW 224
#define PLANE (GHH*GWW)
#define TS 16
#define HALO 3
#define THALO (TS + 2*HALO)    // 22
#define NPIX (THALO*THALO)     // 484
#define CH 32
#define CHP_H 40               // padded half-channel stride: 80B lane stride, conflict-free
#define NP 49

// Scratch (no allocations allowed): f0 after linear, plus ping-pong stage buffers.
__device__ float g_f0[8*972];
__device__ float g_bufA[8*3*PLANE];
__device__ float g_bufB[8*3*PLANE];

__device__ __forceinline__ int refl(int i, int n) {
    if (i < 0) i = -i;
    if (i >= n) i = 2*n - 2 - i;
    return i;
}

__device__ __forceinline__ float gelu_exact(float x) {
    return 0.5f * x * (1.0f + erff(x * 0.7071067811865476f));
}

__device__ __forceinline__ __half2 h2cast(unsigned int u) {
    return *reinterpret_cast<__half2*>(&u);
}

// ---------------------------------------------------------------- linear ----
__global__ void linear_kernel(const float* __restrict__ x,
                              const float* __restrict__ w,
                              const float* __restrict__ bias)
{
    int gw = blockIdx.x * 4 + (threadIdx.x >> 5);
    int lane = threadIdx.x & 31;
    if (gw >= 8*972) return;
    int b = gw / 972, o = gw % 972;
    const float* xr = x + b*1000;
    const float* wr = w + o*1000;
    float s = 0.f;
    for (int k = lane; k < 1000; k += 32) s += xr[k] * wr[k];
    #pragma unroll
    for (int off = 16; off; off >>= 1) s += __shfl_xor_sync(0xffffffffu, s, off);
    if (lane == 0) g_f0[b*972 + o] = s + bias[o];
}

// ---------------------------------------------------------------- bicubic ----
__device__ __forceinline__ float cubicw(float d) {
    d = fabsf(d);
    const float a = -0.75f;
    if (d <= 1.f) return ((a + 2.f)*d - (a + 3.f))*d*d + 1.f;
    if (d <  2.f) return (((d - 5.f)*d + 8.f)*d - 4.f) * a;
    return 0.f;
}

__global__ void bicubic18_kernel()
{
    int idx = blockIdx.x * blockDim.x + threadIdx.x;
    if (idx >= 8*3*PLANE) return;
    int x  = idx % GWW;
    int y  = (idx / GWW) % GHH;
    int bc = idx / PLANE;
    float xs = (x + 0.5f) * (18.0f/224.0f) - 0.5f;
    float ys = (y + 0.5f) * (18.0f/224.0f) - 0.5f;
    int x0 = (int)floorf(xs), y0 = (int)floorf(ys);
    float tx = xs - (float)x0, ty = ys - (float)y0;
    float wx[4], wy[4]; int ix[4], iy[4];
    #pragma unroll
    for (int k = 0; k < 4; k++) {
        wx[k] = cubicw(tx - (float)(k-1)); ix[k] = min(max(x0 + k - 1, 0), 17);
        wy[k] = cubicw(ty - (float)(k-1)); iy[k] = min(max(y0 + k - 1, 0), 17);
    }
    const float* f = g_f0 + bc*324;
    float acc = 0.f;
    #pragma unroll
    for (int i = 0; i < 4; i++) {
        float r = 0.f;
        #pragma unroll
        for (int j = 0; j < 4; j++) r += wx[j] * f[iy[i]*18 + ix[j]];
        acc += wy[i] * r;
    }
    g_bufA[idx] = acc;
}

// ------------------------------------------------------------- fused JBU ----
__global__ __launch_bounds__(256, 2)
void jbu_kernel(const float* __restrict__ guidance,
                const float* __restrict__ w1, const float* __restrict__ b1,
                const float* __restrict__ w2, const float* __restrict__ b2,
                const float* __restrict__ temp_p, const float* __restrict__ sigma_p,
                int src_sel, int dst_sel, float* __restrict__ dst_ext)
{
    const float* hr_in = (src_sel == 0) ? g_bufA : g_bufB;
    float* out = (dst_sel == 2) ? dst_ext : ((dst_sel == 0) ? g_bufA : g_bufB);

    extern __shared__ float smem[];
    // layout (floats): shr [3*NPIX] | weights | sq (half, at the end, 16B aligned)
    float* shr = smem;                  // [3][NPIX]
    float* sw1 = shr + 3*NPIX;          // 96
    float* sb1 = sw1 + 96;              // 32
    float* sw2 = sb1 + 32;              // 1024
    float* sb2 = sw2 + 1024;            // 32
    float* ssp = sb2 + 32;              // 49
    __half* sq = (__half*)(ssp + 49 + 3);   // pad to 16B boundary: (3*484+1233+3)=2688 floats -> 10752B, 16B aligned

    const int tid = threadIdx.x;
    const int b   = blockIdx.z;
    const int ty0 = blockIdx.y * TS, tx0 = blockIdx.x * TS;

    for (int i = tid; i < 96;   i += 256) sw1[i] = w1[i];
    for (int i = tid; i < 1024; i += 256) sw2[i] = w2[i];
    if (tid < 32) { sb1[tid] = b1[tid]; sb2[tid] = b2[tid]; }
    if (tid < NP) {
        float sig = *sigma_p;
        int di = tid / 7, dj = tid % 7;
        float dy = -1.0f + (float)di * (1.0f/3.0f);
        float dx = -1.0f + (float)dj * (1.0f/3.0f);
        ssp[tid] = expf(-(dy*dy + dx*dx) / (2.0f*sig*sig));
    }
    __syncthreads();

    const float* gb = guidance + (size_t)b * 3 * PLANE;
    const float* hb = hr_in    + (size_t)b * 3 * PLANE;

    // Fill halo tile: hr channels (fp32) + q (range_proj of guidance, fp16).
    for (int i = tid; i < NPIX; i += 256) {
        int ly = i / THALO, lx = i % THALO;
        int gy = refl(ty0 + ly - HALO, GHH);
        int gx = refl(tx0 + lx - HALO, GWW);
        int gi = gy * GWW + gx;
        float g0 = gb[gi], g1 = gb[PLANE + gi], g2 = gb[2*PLANE + gi];
        shr[i]        = hb[gi];
        shr[NPIX+i]   = hb[PLANE + gi];
        shr[2*NPIX+i] = hb[2*PLANE + gi];
        float h[CH];
        #pragma unroll
        for (int k = 0; k < CH; k++) {
            float v = sw1[k*3]*g0 + sw1[k*3+1]*g1 + sw1[k*3+2]*g2 + sb1[k];
            h[k] = gelu_exact(v);
        }
        float q[CH];
        #pragma unroll
        for (int j = 0; j < CH; j++) {
            float v = sb2[j];
            const float4* wr = (const float4*)(sw2 + j*CH);
            #pragma unroll
            for (int k4 = 0; k4 < 8; k4++) {
                float4 ww = wr[k4];
                v += ww.x*h[4*k4] + ww.y*h[4*k4+1] + ww.z*h[4*k4+2] + ww.w*h[4*k4+3];
            }
            q[j] = v;
        }
        // pack 32 fp32 -> 16 half2 -> 4 uint4 stores (base 80B*i is 16B aligned)
        uint4* qd = (uint4*)(sq + i * CHP_H);
        #pragma unroll
        for (int k = 0; k < 4; k++) {
            __half2 p0 = __floats2half2_rn(q[8*k+0], q[8*k+1]);
            __half2 p1 = __floats2half2_rn(q[8*k+2], q[8*k+3]);
            __half2 p2 = __floats2half2_rn(q[8*k+4], q[8*k+5]);
            __half2 p3 = __floats2half2_rn(q[8*k+6], q[8*k+7]);
            uint4 u;
            u.x = *reinterpret_cast<unsigned int*>(&p0);
            u.y = *reinterpret_cast<unsigned int*>(&p1);
            u.z = *reinterpret_cast<unsigned int*>(&p2);
            u.w = *reinterpret_cast<unsigned int*>(&p3);
            qd[k] = u;
        }
    }
    __syncthreads();

    const int ty = tid / TS, tx = tid % TS;
    const int base = ty * THALO + tx;                  // top-left (di=0,dj=0) tap
    const __half* qb = sq + base * CHP_H;
    const __half* qc = sq + (base + HALO*THALO + HALO) * CHP_H;

    __half2 s2[NP];
    #pragma unroll
    for (int p = 0; p < NP; p++) s2[p] = __float2half2_rn(0.f);

    #pragma unroll 1
    for (int c4 = 0; c4 < 4; c4++) {           // 8 channels per iteration
        uint4 cu = ((const uint4*)qc)[c4];
        __half2 c0 = h2cast(cu.x), c1 = h2cast(cu.y), c2 = h2cast(cu.z), c3 = h2cast(cu.w);
        #pragma unroll
        for (int p = 0; p < NP; p++) {
            const int di = p / 7, dj = p % 7;
            uint4 tu = ((const uint4*)(qb + (di*THALO + dj)*CHP_H))[c4];
            __half2 acc = s2[p];
            acc = __hfma2(c0, h2cast(tu.x), acc);
            acc = __hfma2(c1, h2cast(tu.y), acc);
            acc = __hfma2(c2, h2cast(tu.z), acc);
            acc = __hfma2(c3, h2cast(tu.w), acc);
            s2[p] = acc;
        }
    }

    float tmp = expf(*temp_p);
    tmp = fminf(fmaxf(tmp, 1e-4f), 1e4f);

    float s[NP];
    float m = -1e30f;
    #pragma unroll
    for (int p = 0; p < NP; p++) {
        float2 f = __half22float2(s2[p]);
        s[p] = (f.x + f.y) * tmp;
        m = fmaxf(m, s[p]);
    }
    float sum = 0.f;
    #pragma unroll
    for (int p = 0; p < NP; p++) {
        float e = __expf(s[p] - m) * ssp[p];
        s[p] = e; sum += e;
    }
    float inv = 1.0f / fmaxf(sum, 1e-7f);

    float o0 = 0.f, o1 = 0.f, o2 = 0.f;
    #pragma unroll
    for (int p = 0; p < NP; p++) {
        const int di = p / 7, dj = p % 7;
        int ti = base + di*THALO + dj;
        o0 += s[p] * shr[ti];
        o1 += s[p] * shr[NPIX + ti];
        o2 += s[p] * shr[2*NPIX + ti];
    }
    int y = ty0 + ty, x = tx0 + tx;
    size_t ob = (size_t)b * 3 * PLANE + (size_t)y * GWW + x;
    out[ob]           = o0 * inv;
    out[ob +   PLANE] = o1 * inv;
    out[ob + 2*PLANE] = o2 * inv;
}

// ----------------------------------------------------------------- launch ----
extern "C" void kernel_launch(void* const* d_in, const int* in_sizes, int n_in,
                              void* d_out, int out_size)
{
    const float* x      = (const float*)d_in[0];
    const float* gd     = (const float*)d_in[1];
    const float* lw     = (const float*)d_in[2];
    const float* lb     = (const float*)d_in[3];
    const float* w1s    = (const float*)d_in[4];
    const float* b1s    = (const float*)d_in[5];
    const float* w2s    = (const float*)d_in[6];
    const float* b2s    = (const float*)d_in[7];
    const float* temps  = (const float*)d_in[8];
    const float* sigmas = (const float*)d_in[9];
    float* out = (float*)d_out;

    // floats: 3*NPIX + 96+32+1024+32+49 + 3 pad = 2688 ; halves: NPIX*CHP_H = 19360
    const int smem = 2688 * 4 + NPIX * CHP_H * 2;   // 10752 + 38720 = 49472 B
    static int smem_set = 0;
    if (!smem_set) {
        cudaFuncSetAttribute(jbu_kernel, cudaFuncAttributeMaxDynamicSharedMemorySize, smem);
        smem_set = 1;
    }

    linear_kernel<<<(8*972 + 3)/4, 128>>>(x, lw, lb);
    bicubic18_kernel<<<(8*3*PLANE + 255)/256, 256>>>();

    dim3 grid(GWW/TS, GHH/TS, 8);
    jbu_kernel<<<grid, 256, smem>>>(gd, w1s + 0*96, b1s + 0*32, w2s + 0*1024, b2s + 0*32,
                                    temps + 0, sigmas + 0, 0, 1, nullptr);
    jbu_kernel<<<grid, 256, smem>>>(gd, w1s + 1*96, b1s + 1*32, w2s + 1*1024, b2s + 1*32,
                                    temps + 1, sigmas + 1, 1, 0, nullptr);
    jbu_kernel<<<grid, 256, smem>>>(gd, w1s + 2*96, b1s + 2*32, w2s + 2*1024, b2s + 2*32,
                                    temps + 2, sigmas + 2, 0, 1, nullptr);
    jbu_kernel<<<grid, 256, smem>>>(gd, w1s + 3*96, b1s + 3*32, w2s + 3*1024, b2s + 3*32,
                                    temps + 3, sigmas + 3, 1, 2, out);
}

// round 5
// speedup vs baseline: 1.7729x; 1.3692x over previous
#include <cuda_runtime.h>
#include <cuda_fp16.h>
#include <math.h>

#define GHH 224
#define GWW 224
#define PLANE (GHH*GWW)
#define TS 16
#define HALO 3
#define THALO (TS + 2*HALO)    // 22
#define NPIX (THALO*THALO)     // 484
#define CH 32
#define CHP_H 40               // padded half-channel stride in smem: 80B lane stride, conflict-free
#define NP 49

// Scratch (no allocations allowed).
__device__ float  g_f0[8*972];
__device__ float  g_bufA[8*3*PLANE];
__device__ float  g_bufB[8*3*PLANE];
__device__ __half g_q[4ull*8*PLANE*CH];   // per-stage projected guidance keys, fp16

__device__ __forceinline__ int refl(int i, int n) {
    if (i < 0) i = -i;
    if (i >= n) i = 2*n - 2 - i;
    return i;
}

__device__ __forceinline__ float gelu_exact(float x) {
    return 0.5f * x * (1.0f + erff(x * 0.7071067811865476f));
}

__device__ __forceinline__ __half2 h2cast(unsigned int u) {
    return *reinterpret_cast<__half2*>(&u);
}

// ---------------------------------------------------------------- linear ----
__global__ void linear_kernel(const float* __restrict__ x,
                              const float* __restrict__ w,
                              const float* __restrict__ bias)
{
    int gw = blockIdx.x * 4 + (threadIdx.x >> 5);
    int lane = threadIdx.x & 31;
    if (gw >= 8*972) return;
    int b = gw / 972, o = gw % 972;
    const float* xr = x + b*1000;
    const float* wr = w + o*1000;
    float s = 0.f;
    for (int k = lane; k < 1000; k += 32) s += xr[k] * wr[k];
    #pragma unroll
    for (int off = 16; off; off >>= 1) s += __shfl_xor_sync(0xffffffffu, s, off);
    if (lane == 0) g_f0[b*972 + o] = s + bias[o];
}

// ---------------------------------------------------------------- bicubic ----
__device__ __forceinline__ float cubicw(float d) {
    d = fabsf(d);
    const float a = -0.75f;
    if (d <= 1.f) return ((a + 2.f)*d - (a + 3.f))*d*d + 1.f;
    if (d <  2.f) return (((d - 5.f)*d + 8.f)*d - 4.f) * a;
    return 0.f;
}

__global__ void bicubic18_kernel()
{
    int idx = blockIdx.x * blockDim.x + threadIdx.x;
    if (idx >= 8*3*PLANE) return;
    int x  = idx % GWW;
    int y  = (idx / GWW) % GHH;
    int bc = idx / PLANE;
    float xs = (x + 0.5f) * (18.0f/224.0f) - 0.5f;
    float ys = (y + 0.5f) * (18.0f/224.0f) - 0.5f;
    int x0 = (int)floorf(xs), y0 = (int)floorf(ys);
    float tx = xs - (float)x0, ty = ys - (float)y0;
    float wx[4], wy[4]; int ix[4], iy[4];
    #pragma unroll
    for (int k = 0; k < 4; k++) {
        wx[k] = cubicw(tx - (float)(k-1)); ix[k] = min(max(x0 + k - 1, 0), 17);
        wy[k] = cubicw(ty - (float)(k-1)); iy[k] = min(max(y0 + k - 1, 0), 17);
    }
    const float* f = g_f0 + bc*324;
    float acc = 0.f;
    #pragma unroll
    for (int i = 0; i < 4; i++) {
        float r = 0.f;
        #pragma unroll
        for (int j = 0; j < 4; j++) r += wx[j] * f[iy[i]*18 + ix[j]];
        acc += wy[i] * r;
    }
    g_bufA[idx] = acc;
}

// --------------------------------------------------------------- q-proj ----
// One launch computes q (range_proj of guidance) for ALL 4 stages, fp16 out.
// g_q layout: [stage][b][pixel][32ch] contiguous (64B per pixel).
__global__ __launch_bounds__(256)
void qproj_kernel(const float* __restrict__ guidance,
                  const float* __restrict__ w1s, const float* __restrict__ b1s,
                  const float* __restrict__ w2s, const float* __restrict__ b2s)
{
    __shared__ float   s_w1[4*96];
    __shared__ float   s_b1[4*32];
    __shared__ float   s_b2[4*32];
    __shared__ __half2 s_w2[4*32*16];   // [stage][out j][k pair]

    const int tid = threadIdx.x;
    for (int i = tid; i < 4*96; i += 256) s_w1[i] = w1s[i];
    for (int i = tid; i < 4*32; i += 256) { s_b1[i] = b1s[i]; s_b2[i] = b2s[i]; }
    for (int i = tid; i < 4*32*16; i += 256) {
        // i = ((s*32 + j)*16 + k) ; source w2s[s][j][2k], [2k+1]
        int k = i & 15; int sj = i >> 4;
        s_w2[i] = __floats2half2_rn(w2s[sj*32 + 2*k], w2s[sj*32 + 2*k + 1]);
    }
    __syncthreads();

    int P = blockIdx.x * 256 + tid;
    if (P >= 8*PLANE) return;
    int b = P / PLANE, gi = P % PLANE;
    const float* gb = guidance + (size_t)b * 3 * PLANE;
    float g0 = gb[gi], g1 = gb[PLANE + gi], g2 = gb[2*PLANE + gi];

    #pragma unroll 1
    for (int s = 0; s < 4; s++) {
        const float* w1 = s_w1 + s*96;
        const float* b1 = s_b1 + s*32;
        const float* b2 = s_b2 + s*32;
        const __half2* w2 = s_w2 + s*32*16;

        __half2 h2[16];
        #pragma unroll
        for (int k = 0; k < 16; k++) {
            float va = w1[(2*k  )*3]*g0 + w1[(2*k  )*3+1]*g1 + w1[(2*k  )*3+2]*g2 + b1[2*k  ];
            float vb = w1[(2*k+1)*3]*g0 + w1[(2*k+1)*3+1]*g1 + w1[(2*k+1)*3+2]*g2 + b1[2*k+1];
            h2[k] = __floats2half2_rn(gelu_exact(va), gelu_exact(vb));
        }
        __half q[CH];
        #pragma unroll
        for (int j = 0; j < CH; j++) {
            __half2 a2 = __float2half2_rn(0.f);
            const __half2* wr = w2 + j*16;
            #pragma unroll
            for (int k = 0; k < 16; k++) a2 = __hfma2(h2[k], wr[k], a2);
            float2 f = __half22float2(a2);
            q[j] = __float2half_rn(f.x + f.y + b2[j]);
        }
        uint4* dst = (uint4*)(g_q + ((size_t)s*8*PLANE + P) * CH);
        const uint4* src = (const uint4*)q;
        dst[0] = src[0]; dst[1] = src[1]; dst[2] = src[2]; dst[3] = src[3];
    }
}

// ------------------------------------------------------------- fused JBU ----
__global__ __launch_bounds__(256, 2)
void jbu_kernel(const float* __restrict__ temp_p, const float* __restrict__ sigma_p,
                int stage, int src_sel, int dst_sel, float* __restrict__ dst_ext)
{
    const float* hr_in = (src_sel == 0) ? g_bufA : g_bufB;
    float* out = (dst_sel == 2) ? dst_ext : ((dst_sel == 0) ? g_bufA : g_bufB);

    extern __shared__ float smem[];
    float* shr = smem;                      // [3][NPIX] = 1452
    float* ssp = shr + 3*NPIX;              // 49 -> 1501
    __half* sq = (__half*)(smem + 1504);    // 16B aligned (1504*4 = 6016)

    const int tid = threadIdx.x;
    const int b   = blockIdx.z;
    const int ty0 = blockIdx.y * TS, tx0 = blockIdx.x * TS;

    if (tid < NP) {
        float sig = *sigma_p;
        int di = tid / 7, dj = tid % 7;
        float dy = -1.0f + (float)di * (1.0f/3.0f);
        float dx = -1.0f + (float)dj * (1.0f/3.0f);
        ssp[tid] = expf(-(dy*dy + dx*dx) / (2.0f*sig*sig));
    }

    const float*  hb = hr_in + (size_t)b * 3 * PLANE;
    const __half* qg = g_q + ((size_t)stage*8 + b) * PLANE * CH;

    // Halo fill: hr (fp32) + precomputed q (fp16, straight copy gmem->smem).
    for (int i = tid; i < NPIX; i += 256) {
        int ly = i / THALO, lx = i % THALO;
        int gy = refl(ty0 + ly - HALO, GHH);
        int gx = refl(tx0 + lx - HALO, GWW);
        int gi = gy * GWW + gx;
        shr[i]        = hb[gi];
        shr[NPIX+i]   = hb[PLANE + gi];
        shr[2*NPIX+i] = hb[2*PLANE + gi];
        const uint4* qs = (const uint4*)(qg + (size_t)gi * CH);
        uint4* qd = (uint4*)(sq + i * CHP_H);
        qd[0] = qs[0]; qd[1] = qs[1]; qd[2] = qs[2]; qd[3] = qs[3];
    }
    __syncthreads();

    const int ty = tid / TS, tx = tid % TS;
    const int base = ty * THALO + tx;                  // top-left (di=0,dj=0) tap
    const __half* qb = sq + base * CHP_H;
    const __half* qc = sq + (base + HALO*THALO + HALO) * CHP_H;

    __half2 s2[NP];
    #pragma unroll
    for (int p = 0; p < NP; p++) s2[p] = __float2half2_rn(0.f);

    #pragma unroll 1
    for (int c4 = 0; c4 < 4; c4++) {           // 8 channels per iteration
        uint4 cu = ((const uint4*)qc)[c4];
        __half2 c0 = h2cast(cu.x), c1 = h2cast(cu.y), c2 = h2cast(cu.z), c3 = h2cast(cu.w);
        #pragma unroll
        for (int p = 0; p < NP; p++) {
            const int di = p / 7, dj = p % 7;
            uint4 tu = ((const uint4*)(qb + (di*THALO + dj)*CHP_H))[c4];
            __half2 acc = s2[p];
            acc = __hfma2(c0, h2cast(tu.x), acc);
            acc = __hfma2(c1, h2cast(tu.y), acc);
            acc = __hfma2(c2, h2cast(tu.z), acc);
            acc = __hfma2(c3, h2cast(tu.w), acc);
            s2[p] = acc;
        }
    }

    float tmp = expf(*temp_p);
    tmp = fminf(fmaxf(tmp, 1e-4f), 1e4f);

    float s[NP];
    float m = -1e30f;
    #pragma unroll
    for (int p = 0; p < NP; p++) {
        float2 f = __half22float2(s2[p]);
        s[p] = (f.x + f.y) * tmp;
        m = fmaxf(m, s[p]);
    }
    float sum = 0.f;
    #pragma unroll
    for (int p = 0; p < NP; p++) {
        float e = __expf(s[p] - m) * ssp[p];
        s[p] = e; sum += e;
    }
    float inv = 1.0f / fmaxf(sum, 1e-7f);

    float o0 = 0.f, o1 = 0.f, o2 = 0.f;
    #pragma unroll
    for (int p = 0; p < NP; p++) {
        const int di = p / 7, dj = p % 7;
        int ti = base + di*THALO + dj;
        o0 += s[p] * shr[ti];
        o1 += s[p] * shr[NPIX + ti];
        o2 += s[p] * shr[2*NPIX + ti];
    }
    int y = ty0 + ty, x = tx0 + tx;
    size_t ob = (size_t)b * 3 * PLANE + (size_t)y * GWW + x;
    out[ob]           = o0 * inv;
    out[ob +   PLANE] = o1 * inv;
    out[ob + 2*PLANE] = o2 * inv;
}

// ----------------------------------------------------------------- launch ----
extern "C" void kernel_launch(void* const* d_in, const int* in_sizes, int n_in,
                              void* d_out, int out_size)
{
    const float* x      = (const float*)d_in[0];
    const float* gd     = (const float*)d_in[1];
    const float* lw     = (const float*)d_in[2];
    const float* lb     = (const float*)d_in[3];
    const float* w1s    = (const float*)d_in[4];
    const float* b1s    = (const float*)d_in[5];
    const float* w2s    = (const float*)d_in[6];
    const float* b2s    = (const float*)d_in[7];
    const float* temps  = (const float*)d_in[8];
    const float* sigmas = (const float*)d_in[9];
    float* out = (float*)d_out;

    const int smem = 1504*4 + NPIX * CHP_H * 2;   // 6016 + 38720 = 44736 B
    static int smem_set = 0;
    if (!smem_set) {
        cudaFuncSetAttribute(jbu_kernel, cudaFuncAttributeMaxDynamicSharedMemorySize, smem);
        smem_set = 1;
    }

    linear_kernel<<<(8*972 + 3)/4, 128>>>(x, lw, lb);
    bicubic18_kernel<<<(8*3*PLANE + 255)/256, 256>>>();
    qproj_kernel<<<(8*PLANE + 255)/256, 256>>>(gd, w1s, b1s, w2s, b2s);

    dim3 grid(GWW/TS, GHH/TS, 8);
    jbu_kernel<<<grid, 256, smem>>>(temps + 0, sigmas + 0, 0, 0, 1, nullptr);
    jbu_kernel<<<grid, 256, smem>>>(temps + 1, sigmas + 1, 1, 1, 0, nullptr);
    jbu_kernel<<<grid, 256, smem>>>(temps + 2, sigmas + 2, 2, 0, 1, nullptr);
    jbu_kernel<<<grid, 256, smem>>>(temps + 3, sigmas + 3, 3, 1, 2, out);
}